// round 6
// baseline (speedup 1.0000x reference)
#include <cuda_runtime.h>

// ---------------------------------------------------------------------------
// QuantumHybridHead, Heisenberg-picture reduction (see R2 derivation).
// z0 = c0 <Z1 Z2 Z3> + s0 <X0 Y1 Z2 Z3>
// z1 = c1 <Z0 Z1>    + s1 <Z0 Y1 X2>
// z2 = c2 <Z0 Z1 Z2> + s2 <Z0 Z1 Y2 X3>
// z3 = c3 <Z0Z1Z2Z3> - s3 <Y0 Y1 Z2 Y3>
// Product state => per-wire affine expectations E(w) = p + q cos w + r sin w.
// R5: per-WARP constant precompute (no __syncthreads, no cross-warp coupling),
// plain stores (shorter EXIT drain), front-batched loads, exact-division path.
// ---------------------------------------------------------------------------

struct Cpx { float re, im; };

__device__ __forceinline__ Cpx cmul(Cpx a, Cpx b) {
    return { a.re * b.re - a.im * b.im, a.re * b.im + a.im * b.re };
}
__device__ __forceinline__ Cpx cconjmul(Cpx a, Cpx b) {  // conj(a)*b
    return { a.re * b.re + a.im * b.im, a.re * b.im - a.im * b.re };
}

// G = Rz(th[2]) * Ry(th[1]) * Rx(th[0])
__device__ __forceinline__ void gateG(const float* __restrict__ th,
                                      Cpx& g00, Cpx& g01, Cpx& g10, Cpx& g11) {
    float cx, sx, cy, sy, cz, sz;
    __sincosf(0.5f * th[0], &sx, &cx);
    __sincosf(0.5f * th[1], &sy, &cy);
    __sincosf(0.5f * th[2], &sz, &cz);
    Cpx m00 = { cy * cx,  sy * sx };
    Cpx m01 = { -sy * cx, -cy * sx };
    Cpx m10 = { sy * cx,  -cy * sx };
    Cpx m11 = { cy * cx,  -sy * sx };
    Cpx e0 = { cz, -sz };
    Cpx e1 = { cz,  sz };
    g00 = cmul(e0, m00); g01 = cmul(e0, m01);
    g10 = cmul(e1, m10); g11 = cmul(e1, m11);
}

// tmp[0..8] = pZ qZ rZ pX qX rX pY qY rY
__device__ __forceinline__ void wireConsts(Cpx g00, Cpx g01, Cpx g10, Cpx g11,
                                           bool k_minus_i, float* tmp) {
    float n00 = g00.re * g00.re + g00.im * g00.im;
    float n01 = g01.re * g01.re + g01.im * g01.im;
    float n10 = g10.re * g10.re + g10.im * g10.im;
    float n11 = g11.re * g11.re + g11.im * g11.im;
    float AZ = n00 - n10, BZ = n01 - n11;
    Cpx a01 = cconjmul(g00, g01);
    Cpx b01 = cconjmul(g10, g11);
    Cpx CZ = { a01.re - b01.re, a01.im - b01.im };
    Cpx c00 = cconjmul(g00, g10);
    Cpx c01 = cconjmul(g01, g11);
    float AX = 2.0f * c00.re, BX = 2.0f * c01.re;
    Cpx t1 = cconjmul(g00, g11);
    Cpx t2 = cconjmul(g10, g01);
    Cpx CX = { t1.re + t2.re, t1.im + t2.im };
    float AY = 2.0f * c00.im, BY = 2.0f * c01.im;
    Cpx D = { t2.re - t1.re, t2.im - t1.im };
    Cpx CY = { -D.im, D.re };                   // i*D
    tmp[0] = 0.5f * (AZ + BZ); tmp[1] = 0.5f * (AZ - BZ);
    tmp[2] = k_minus_i ? CZ.im : CZ.re;
    tmp[3] = 0.5f * (AX + BX); tmp[4] = 0.5f * (AX - BX);
    tmp[5] = k_minus_i ? CX.im : CX.re;
    tmp[6] = 0.5f * (AY + BY); tmp[7] = 0.5f * (AY - BY);
    tmp[8] = k_minus_i ? CY.im : CY.re;
}

// Per-warp const layout (32 floats):
//  [0..8]   wire0: Z(p,q,r) X(p,q,r) Y(p,q,r)
//  [9..14]  wire1: Z(p,q,r) Y(p,q,r)
//  [15..23] wire3: Z(p,q,r) X(p,q,r) Y(p,q,r)
//  [24..31] A0 B0 A1 B1 A2a A2b A3 B3
__device__ __forceinline__ void precompute_warp(const float* __restrict__ theta,
                                                float* __restrict__ scw, int lane) {
    if (lane < 4) {
        if (lane < 3) {
            // lane 0 -> wire0 (rx enc), lane 1 -> wire1 (ry enc), lane 2 -> wire3
            int q = (lane == 2) ? 3 : lane;
            Cpx g00, g01, g10, g11;
            gateG(theta + 3 * q, g00, g01, g10, g11);
            float tmp[9];
            wireConsts(g00, g01, g10, g11, lane != 1, tmp);
            if (lane == 0) {
                #pragma unroll
                for (int k = 0; k < 9; k++) scw[k] = tmp[k];
            } else if (lane == 1) {
                scw[9]  = tmp[0]; scw[10] = tmp[1]; scw[11] = tmp[2];
                scw[12] = tmp[6]; scw[13] = tmp[7]; scw[14] = tmp[8];
            } else {
                #pragma unroll
                for (int k = 0; k < 9; k++) scw[15 + k] = tmp[k];
            }
        } else {
            // lane 3: wire-2 constant expectations + final-rx folds
            Cpx g00, g01, g10, g11;
            gateG(theta + 6, g00, g01, g10, g11);
            // u2 = G2 |0> = (g00, g10)
            float z2c = (g00.re * g00.re + g00.im * g00.im)
                      - (g10.re * g10.re + g10.im * g10.im);
            Cpx cr = cconjmul(g00, g10);
            float x2c = 2.0f * cr.re;
            float y2c = 2.0f * cr.im;
            float cw[4], sw[4];
            #pragma unroll
            for (int q = 0; q < 4; q++) __sincosf(theta[12 + q], &sw[q], &cw[q]);
            scw[24] = cw[0] * z2c;  // A0
            scw[25] = sw[0] * z2c;  // B0
            scw[26] = cw[1];        // A1
            scw[27] = sw[1] * x2c;  // B1
            scw[28] = cw[2] * z2c;  // A2a
            scw[29] = sw[2] * y2c;  // A2b
            scw[30] = cw[3] * z2c;  // A3
            scw[31] = sw[3] * z2c;  // B3
        }
    }
}

__device__ __forceinline__ float4 sample(const float* __restrict__ C, float4 w) {
    float cw0, sw0, cw1, sw1, cw3, sw3;
    __sincosf(w.x, &sw0, &cw0);
    __sincosf(w.y, &sw1, &cw1);
    __sincosf(w.w, &sw3, &cw3);
    float z0 = fmaf(C[1],  cw0, fmaf(C[2],  sw0, C[0]));
    float x0 = fmaf(C[4],  cw0, fmaf(C[5],  sw0, C[3]));
    float y0 = fmaf(C[7],  cw0, fmaf(C[8],  sw0, C[6]));
    float z1 = fmaf(C[10], cw1, fmaf(C[11], sw1, C[9]));
    float y1 = fmaf(C[13], cw1, fmaf(C[14], sw1, C[12]));
    float z3 = fmaf(C[16], cw3, fmaf(C[17], sw3, C[15]));
    float x3 = fmaf(C[19], cw3, fmaf(C[20], sw3, C[18]));
    float y3 = fmaf(C[22], cw3, fmaf(C[23], sw3, C[21]));
    float z01 = z0 * z1;
    float4 o;
    o.x = z3  * fmaf(C[25], x0 * y1, C[24] * z1);
    o.y = z0  * fmaf(C[27], y1,      C[26] * z1);
    o.z = z01 * fmaf(C[29], x3,      C[28]);
    o.w = fmaf(C[30], z01 * z3, -(C[31] * (y0 * y1) * y3));
    return o;
}

static constexpr int SPT = 4;      // samples per thread
static constexpr int NTHR = 128;   // threads per block (4 warps)

template <bool CHECKED>
__global__ void __launch_bounds__(NTHR)
qsim_kernel(const float4* __restrict__ inp, const float* __restrict__ theta,
            float4* __restrict__ out, int n, int nthreads) {
    __shared__ float sc[4][32];    // one 32-float slab per warp
    int t = threadIdx.x;
    int wid = t >> 5;
    int lane = t & 31;
    int tid = blockIdx.x * NTHR + t;

    // ---- Front-batch the input loads (independent of the constants). ----
    float4 w[SPT];
    #pragma unroll
    for (int k = 0; k < SPT; k++) {
        int i = tid + k * nthreads;
        if (!CHECKED || i < n) w[k] = __ldg(&inp[i]);
    }

    // ---- Per-WARP constant precompute: lanes 0..3, __syncwarp only.
    //      No block barrier -> warps fully decoupled. ----
    precompute_warp(theta, sc[wid], lane);
    __syncwarp();

    float C[32];
    #pragma unroll
    for (int k = 0; k < 32; k++) C[k] = sc[wid][k];

    // ---- Compute + store per sample (plain STG: L2-visible, short drain) ----
    #pragma unroll
    for (int k = 0; k < SPT; k++) {
        int i = tid + k * nthreads;
        if (!CHECKED || i < n) {
            float4 o = sample(C, w[k]);
            out[i] = o;
        }
    }
}

extern "C" void kernel_launch(void* const* d_in, const int* in_sizes, int n_in,
                              void* d_out, int out_size) {
    const float* inputs = (const float*)d_in[0];   // [B, 4] float32
    const float* theta  = (const float*)d_in[1];   // [16] float32
    float* out = (float*)d_out;                    // [B, 4, 1] float32

    int n = in_sizes[0] / 4;                 // samples
    int per = (n + SPT - 1) / SPT;           // samples per lane-index slot
    int blocks = (per + NTHR - 1) / NTHR;
    int nthreads = blocks * NTHR;

    if (nthreads * SPT == n) {
        // Exact division (B = 2^19 hits this): no bounds checks on hot path.
        qsim_kernel<false><<<blocks, NTHR>>>((const float4*)inputs, theta,
                                             (float4*)out, n, nthreads);
    } else {
        qsim_kernel<true><<<blocks, NTHR>>>((const float4*)inputs, theta,
                                            (float4*)out, n, nthreads);
    }
}

// round 7
// speedup vs baseline: 1.0037x; 1.0037x over previous
#include <cuda_runtime.h>

// ---------------------------------------------------------------------------
// QuantumHybridHead, Heisenberg-picture reduction (see R2 derivation).
// z0 = c0 <Z1 Z2 Z3> + s0 <X0 Y1 Z2 Z3>
// z1 = c1 <Z0 Z1>    + s1 <Z0 Y1 X2>
// z2 = c2 <Z0 Z1 Z2> + s2 <Z0 Z1 Y2 X3>
// z3 = c3 <Z0Z1Z2Z3> - s3 <Y0 Y1 Z2 Y3>
// Product state => per-wire affine expectations E(w) = p + q cos w + r sin w.
// R6: SPT=8 (deep per-thread ILP: 8 front-batched LDG.128 + 8 independent
// compute chains per thread), 64-thread blocks x 1024 (balanced wave),
// R3-style block-level precompute (hidden under load latency), plain stores.
// ---------------------------------------------------------------------------

struct Cpx { float re, im; };

__device__ __forceinline__ Cpx cmul(Cpx a, Cpx b) {
    return { a.re * b.re - a.im * b.im, a.re * b.im + a.im * b.re };
}
__device__ __forceinline__ Cpx cconjmul(Cpx a, Cpx b) {  // conj(a)*b
    return { a.re * b.re + a.im * b.im, a.re * b.im - a.im * b.re };
}

// G = Rz(th[2]) * Ry(th[1]) * Rx(th[0])
__device__ __forceinline__ void gateG(const float* __restrict__ th,
                                      Cpx& g00, Cpx& g01, Cpx& g10, Cpx& g11) {
    float cx, sx, cy, sy, cz, sz;
    __sincosf(0.5f * th[0], &sx, &cx);
    __sincosf(0.5f * th[1], &sy, &cy);
    __sincosf(0.5f * th[2], &sz, &cz);
    Cpx m00 = { cy * cx,  sy * sx };
    Cpx m01 = { -sy * cx, -cy * sx };
    Cpx m10 = { sy * cx,  -cy * sx };
    Cpx m11 = { cy * cx,  -sy * sx };
    Cpx e0 = { cz, -sz };
    Cpx e1 = { cz,  sz };
    g00 = cmul(e0, m00); g01 = cmul(e0, m01);
    g10 = cmul(e1, m10); g11 = cmul(e1, m11);
}

// tmp[0..8] = pZ qZ rZ pX qX rX pY qY rY
__device__ __forceinline__ void wireConsts(Cpx g00, Cpx g01, Cpx g10, Cpx g11,
                                           bool k_minus_i, float* tmp) {
    float n00 = g00.re * g00.re + g00.im * g00.im;
    float n01 = g01.re * g01.re + g01.im * g01.im;
    float n10 = g10.re * g10.re + g10.im * g10.im;
    float n11 = g11.re * g11.re + g11.im * g11.im;
    float AZ = n00 - n10, BZ = n01 - n11;
    Cpx a01 = cconjmul(g00, g01);
    Cpx b01 = cconjmul(g10, g11);
    Cpx CZ = { a01.re - b01.re, a01.im - b01.im };
    Cpx c00 = cconjmul(g00, g10);
    Cpx c01 = cconjmul(g01, g11);
    float AX = 2.0f * c00.re, BX = 2.0f * c01.re;
    Cpx t1 = cconjmul(g00, g11);
    Cpx t2 = cconjmul(g10, g01);
    Cpx CX = { t1.re + t2.re, t1.im + t2.im };
    float AY = 2.0f * c00.im, BY = 2.0f * c01.im;
    Cpx D = { t2.re - t1.re, t2.im - t1.im };
    Cpx CY = { -D.im, D.re };                   // i*D
    tmp[0] = 0.5f * (AZ + BZ); tmp[1] = 0.5f * (AZ - BZ);
    tmp[2] = k_minus_i ? CZ.im : CZ.re;
    tmp[3] = 0.5f * (AX + BX); tmp[4] = 0.5f * (AX - BX);
    tmp[5] = k_minus_i ? CX.im : CX.re;
    tmp[6] = 0.5f * (AY + BY); tmp[7] = 0.5f * (AY - BY);
    tmp[8] = k_minus_i ? CY.im : CY.re;
}

// Const layout:
//  [0..8]   wire0: Z(p,q,r) X(p,q,r) Y(p,q,r)
//  [9..14]  wire1: Z(p,q,r) Y(p,q,r)
//  [15..23] wire3: Z(p,q,r) X(p,q,r) Y(p,q,r)
//  [24..31] A0 B0 A1 B1 A2a A2b A3 B3
__device__ __forceinline__ void precompute_block(const float* __restrict__ theta,
                                                 float* __restrict__ sc, int t) {
    if (t < 4) {
        if (t < 3) {
            int q = (t == 2) ? 3 : t;
            Cpx g00, g01, g10, g11;
            gateG(theta + 3 * q, g00, g01, g10, g11);
            float tmp[9];
            wireConsts(g00, g01, g10, g11, t != 1, tmp);
            if (t == 0) {
                #pragma unroll
                for (int k = 0; k < 9; k++) sc[k] = tmp[k];
            } else if (t == 1) {
                sc[9]  = tmp[0]; sc[10] = tmp[1]; sc[11] = tmp[2];
                sc[12] = tmp[6]; sc[13] = tmp[7]; sc[14] = tmp[8];
            } else {
                #pragma unroll
                for (int k = 0; k < 9; k++) sc[15 + k] = tmp[k];
            }
        } else {
            Cpx g00, g01, g10, g11;
            gateG(theta + 6, g00, g01, g10, g11);
            // u2 = G2 |0> = (g00, g10)
            float z2c = (g00.re * g00.re + g00.im * g00.im)
                      - (g10.re * g10.re + g10.im * g10.im);
            Cpx cr = cconjmul(g00, g10);
            float x2c = 2.0f * cr.re;
            float y2c = 2.0f * cr.im;
            float cw[4], sw[4];
            #pragma unroll
            for (int q = 0; q < 4; q++) __sincosf(theta[12 + q], &sw[q], &cw[q]);
            sc[24] = cw[0] * z2c;  // A0
            sc[25] = sw[0] * z2c;  // B0
            sc[26] = cw[1];        // A1
            sc[27] = sw[1] * x2c;  // B1
            sc[28] = cw[2] * z2c;  // A2a
            sc[29] = sw[2] * y2c;  // A2b
            sc[30] = cw[3] * z2c;  // A3
            sc[31] = sw[3] * z2c;  // B3
        }
    }
}

__device__ __forceinline__ float4 sample(const float* __restrict__ C, float4 w) {
    float cw0, sw0, cw1, sw1, cw3, sw3;
    __sincosf(w.x, &sw0, &cw0);
    __sincosf(w.y, &sw1, &cw1);
    __sincosf(w.w, &sw3, &cw3);
    float z0 = fmaf(C[1],  cw0, fmaf(C[2],  sw0, C[0]));
    float x0 = fmaf(C[4],  cw0, fmaf(C[5],  sw0, C[3]));
    float y0 = fmaf(C[7],  cw0, fmaf(C[8],  sw0, C[6]));
    float z1 = fmaf(C[10], cw1, fmaf(C[11], sw1, C[9]));
    float y1 = fmaf(C[13], cw1, fmaf(C[14], sw1, C[12]));
    float z3 = fmaf(C[16], cw3, fmaf(C[17], sw3, C[15]));
    float x3 = fmaf(C[19], cw3, fmaf(C[20], sw3, C[18]));
    float y3 = fmaf(C[22], cw3, fmaf(C[23], sw3, C[21]));
    float z01 = z0 * z1;
    float4 o;
    o.x = z3  * fmaf(C[25], x0 * y1, C[24] * z1);
    o.y = z0  * fmaf(C[27], y1,      C[26] * z1);
    o.z = z01 * fmaf(C[29], x3,      C[28]);
    o.w = fmaf(C[30], z01 * z3, -(C[31] * (y0 * y1) * y3));
    return o;
}

static constexpr int SPT  = 8;    // samples per thread (deep ILP)
static constexpr int NTHR = 64;   // threads per block (2 warps, fine-grain balance)

template <bool CHECKED>
__global__ void __launch_bounds__(NTHR)
qsim_kernel(const float4* __restrict__ inp, const float* __restrict__ theta,
            float4* __restrict__ out, int n, int nthreads) {
    __shared__ float sc[32];
    int t = threadIdx.x;
    int tid = blockIdx.x * NTHR + t;

    // ---- Front-batch all SPT input loads (independent of the constants);
    //      the precompute chain + barrier below hide under this latency. ----
    float4 w[SPT];
    #pragma unroll
    for (int k = 0; k < SPT; k++) {
        int i = tid + k * nthreads;
        if (!CHECKED || i < n) w[k] = __ldg(&inp[i]);
    }

    // ---- Block-level constant precompute (threads 0..3) ----
    precompute_block(theta, sc, t);
    __syncthreads();

    float C[32];
    #pragma unroll
    for (int k = 0; k < 32; k++) C[k] = sc[k];

    // ---- 8 independent compute chains; store each sample as it finishes ----
    #pragma unroll
    for (int k = 0; k < SPT; k++) {
        int i = tid + k * nthreads;
        if (!CHECKED || i < n) {
            float4 o = sample(C, w[k]);
            out[i] = o;
        }
    }
}

extern "C" void kernel_launch(void* const* d_in, const int* in_sizes, int n_in,
                              void* d_out, int out_size) {
    const float* inputs = (const float*)d_in[0];   // [B, 4] float32
    const float* theta  = (const float*)d_in[1];   // [16] float32
    float* out = (float*)d_out;                    // [B, 4, 1] float32

    int n = in_sizes[0] / 4;                 // samples
    int per = (n + SPT - 1) / SPT;           // samples per lane-index slot
    int blocks = (per + NTHR - 1) / NTHR;    // 1024 for B = 2^19
    int nthreads = blocks * NTHR;

    if (nthreads * SPT == n) {
        // Exact division (B = 2^19 hits this): no bounds checks on hot path.
        qsim_kernel<false><<<blocks, NTHR>>>((const float4*)inputs, theta,
                                             (float4*)out, n, nthreads);
    } else {
        qsim_kernel<true><<<blocks, NTHR>>>((const float4*)inputs, theta,
                                            (float4*)out, n, nthreads);
    }
}

// round 8
// speedup vs baseline: 1.3077x; 1.3029x over previous
#include <cuda_runtime.h>

// ---------------------------------------------------------------------------
// QuantumHybridHead, Heisenberg-picture reduction (see R2 derivation).
// z0 = c0 <Z1 Z2 Z3> + s0 <X0 Y1 Z2 Z3>
// z1 = c1 <Z0 Z1>    + s1 <Z0 Y1 X2>
// z2 = c2 <Z0 Z1 Z2> + s2 <Z0 Z1 Y2 X3>
// z3 = c3 <Z0Z1Z2Z3> - s3 <Y0 Y1 Z2 Y3>
// Product state => per-wire affine expectations E(w) = p + q cos w + r sin w.
// R7: re-land best-measured config (R3: 256thr x 512blk, SPT=4), constants
// re-read as 8x LDS.128, zero bounds math on the exact-division path.
// ---------------------------------------------------------------------------

struct Cpx { float re, im; };

__device__ __forceinline__ Cpx cmul(Cpx a, Cpx b) {
    return { a.re * b.re - a.im * b.im, a.re * b.im + a.im * b.re };
}
__device__ __forceinline__ Cpx cconjmul(Cpx a, Cpx b) {  // conj(a)*b
    return { a.re * b.re + a.im * b.im, a.re * b.im - a.im * b.re };
}

// G = Rz(th[2]) * Ry(th[1]) * Rx(th[0])
__device__ __forceinline__ void gateG(const float* __restrict__ th,
                                      Cpx& g00, Cpx& g01, Cpx& g10, Cpx& g11) {
    float cx, sx, cy, sy, cz, sz;
    __sincosf(0.5f * th[0], &sx, &cx);
    __sincosf(0.5f * th[1], &sy, &cy);
    __sincosf(0.5f * th[2], &sz, &cz);
    Cpx m00 = { cy * cx,  sy * sx };
    Cpx m01 = { -sy * cx, -cy * sx };
    Cpx m10 = { sy * cx,  -cy * sx };
    Cpx m11 = { cy * cx,  -sy * sx };
    Cpx e0 = { cz, -sz };
    Cpx e1 = { cz,  sz };
    g00 = cmul(e0, m00); g01 = cmul(e0, m01);
    g10 = cmul(e1, m10); g11 = cmul(e1, m11);
}

// tmp[0..8] = pZ qZ rZ pX qX rX pY qY rY
__device__ __forceinline__ void wireConsts(Cpx g00, Cpx g01, Cpx g10, Cpx g11,
                                           bool k_minus_i, float* tmp) {
    float n00 = g00.re * g00.re + g00.im * g00.im;
    float n01 = g01.re * g01.re + g01.im * g01.im;
    float n10 = g10.re * g10.re + g10.im * g10.im;
    float n11 = g11.re * g11.re + g11.im * g11.im;
    float AZ = n00 - n10, BZ = n01 - n11;
    Cpx a01 = cconjmul(g00, g01);
    Cpx b01 = cconjmul(g10, g11);
    Cpx CZ = { a01.re - b01.re, a01.im - b01.im };
    Cpx c00 = cconjmul(g00, g10);
    Cpx c01 = cconjmul(g01, g11);
    float AX = 2.0f * c00.re, BX = 2.0f * c01.re;
    Cpx t1 = cconjmul(g00, g11);
    Cpx t2 = cconjmul(g10, g01);
    Cpx CX = { t1.re + t2.re, t1.im + t2.im };
    float AY = 2.0f * c00.im, BY = 2.0f * c01.im;
    Cpx D = { t2.re - t1.re, t2.im - t1.im };
    Cpx CY = { -D.im, D.re };                   // i*D
    tmp[0] = 0.5f * (AZ + BZ); tmp[1] = 0.5f * (AZ - BZ);
    tmp[2] = k_minus_i ? CZ.im : CZ.re;
    tmp[3] = 0.5f * (AX + BX); tmp[4] = 0.5f * (AX - BX);
    tmp[5] = k_minus_i ? CX.im : CX.re;
    tmp[6] = 0.5f * (AY + BY); tmp[7] = 0.5f * (AY - BY);
    tmp[8] = k_minus_i ? CY.im : CY.re;
}

// Const layout (32 floats, 16B-aligned for LDS.128 reads):
//  [0..8]   wire0: Z(p,q,r) X(p,q,r) Y(p,q,r)
//  [9..14]  wire1: Z(p,q,r) Y(p,q,r)
//  [15..23] wire3: Z(p,q,r) X(p,q,r) Y(p,q,r)
//  [24..31] A0 B0 A1 B1 A2a A2b A3 B3
__device__ __forceinline__ void precompute_block(const float* __restrict__ theta,
                                                 float* __restrict__ sc, int t) {
    if (t < 4) {
        if (t < 3) {
            int q = (t == 2) ? 3 : t;
            Cpx g00, g01, g10, g11;
            gateG(theta + 3 * q, g00, g01, g10, g11);
            float tmp[9];
            wireConsts(g00, g01, g10, g11, t != 1, tmp);
            if (t == 0) {
                #pragma unroll
                for (int k = 0; k < 9; k++) sc[k] = tmp[k];
            } else if (t == 1) {
                sc[9]  = tmp[0]; sc[10] = tmp[1]; sc[11] = tmp[2];
                sc[12] = tmp[6]; sc[13] = tmp[7]; sc[14] = tmp[8];
            } else {
                #pragma unroll
                for (int k = 0; k < 9; k++) sc[15 + k] = tmp[k];
            }
        } else {
            Cpx g00, g01, g10, g11;
            gateG(theta + 6, g00, g01, g10, g11);
            // u2 = G2 |0> = (g00, g10)
            float z2c = (g00.re * g00.re + g00.im * g00.im)
                      - (g10.re * g10.re + g10.im * g10.im);
            Cpx cr = cconjmul(g00, g10);
            float x2c = 2.0f * cr.re;
            float y2c = 2.0f * cr.im;
            float cw[4], sw[4];
            #pragma unroll
            for (int q = 0; q < 4; q++) __sincosf(theta[12 + q], &sw[q], &cw[q]);
            sc[24] = cw[0] * z2c;  // A0
            sc[25] = sw[0] * z2c;  // B0
            sc[26] = cw[1];        // A1
            sc[27] = sw[1] * x2c;  // B1
            sc[28] = cw[2] * z2c;  // A2a
            sc[29] = sw[2] * y2c;  // A2b
            sc[30] = cw[3] * z2c;  // A3
            sc[31] = sw[3] * z2c;  // B3
        }
    }
}

__device__ __forceinline__ float4 sample(const float* __restrict__ C, float4 w) {
    float cw0, sw0, cw1, sw1, cw3, sw3;
    __sincosf(w.x, &sw0, &cw0);
    __sincosf(w.y, &sw1, &cw1);
    __sincosf(w.w, &sw3, &cw3);
    float z0 = fmaf(C[1],  cw0, fmaf(C[2],  sw0, C[0]));
    float x0 = fmaf(C[4],  cw0, fmaf(C[5],  sw0, C[3]));
    float y0 = fmaf(C[7],  cw0, fmaf(C[8],  sw0, C[6]));
    float z1 = fmaf(C[10], cw1, fmaf(C[11], sw1, C[9]));
    float y1 = fmaf(C[13], cw1, fmaf(C[14], sw1, C[12]));
    float z3 = fmaf(C[16], cw3, fmaf(C[17], sw3, C[15]));
    float x3 = fmaf(C[19], cw3, fmaf(C[20], sw3, C[18]));
    float y3 = fmaf(C[22], cw3, fmaf(C[23], sw3, C[21]));
    float z01 = z0 * z1;
    float4 o;
    o.x = z3  * fmaf(C[25], x0 * y1, C[24] * z1);
    o.y = z0  * fmaf(C[27], y1,      C[26] * z1);
    o.z = z01 * fmaf(C[29], x3,      C[28]);
    o.w = fmaf(C[30], z01 * z3, -(C[31] * (y0 * y1) * y3));
    return o;
}

static constexpr int SPT  = 4;     // samples per thread (best measured)
static constexpr int NTHR = 256;   // threads per block (best measured)

template <bool CHECKED>
__global__ void __launch_bounds__(NTHR)
qsim_kernel(const float4* __restrict__ inp, const float* __restrict__ theta,
            float4* __restrict__ out, int n, int nthreads) {
    __shared__ __align__(16) float sc[32];
    int t = threadIdx.x;
    int tid = blockIdx.x * NTHR + t;

    // ---- Front-batch all SPT input loads (independent of the constants);
    //      the precompute chain + barrier hide under this latency. ----
    float4 w[SPT];
    #pragma unroll
    for (int k = 0; k < SPT; k++) {
        int i = tid + k * nthreads;
        if (!CHECKED || i < n) w[k] = __ldg(&inp[i]);
    }

    // ---- Block-level constant precompute (threads 0..3) ----
    precompute_block(theta, sc, t);
    __syncthreads();

    // Re-read constants as 8x LDS.128 (broadcast, conflict-free).
    float C[32];
    #pragma unroll
    for (int k = 0; k < 8; k++) {
        float4 v = reinterpret_cast<const float4*>(sc)[k];
        C[4 * k + 0] = v.x; C[4 * k + 1] = v.y;
        C[4 * k + 2] = v.z; C[4 * k + 3] = v.w;
    }

    // ---- Compute + store per sample ----
    #pragma unroll
    for (int k = 0; k < SPT; k++) {
        int i = tid + k * nthreads;
        if (!CHECKED || i < n) {
            float4 o = sample(C, w[k]);
            out[i] = o;
        }
    }
}

extern "C" void kernel_launch(void* const* d_in, const int* in_sizes, int n_in,
                              void* d_out, int out_size) {
    const float* inputs = (const float*)d_in[0];   // [B, 4] float32
    const float* theta  = (const float*)d_in[1];   // [16] float32
    float* out = (float*)d_out;                    // [B, 4, 1] float32

    int n = in_sizes[0] / 4;                 // samples
    int per = (n + SPT - 1) / SPT;           // samples per lane-index slot
    int blocks = (per + NTHR - 1) / NTHR;    // 512 for B = 2^19
    int nthreads = blocks * NTHR;

    if (nthreads * SPT == n) {
        // Exact division (B = 2^19 hits this): no bounds checks on hot path.
        qsim_kernel<false><<<blocks, NTHR>>>((const float4*)inputs, theta,
                                             (float4*)out, n, nthreads);
    } else {
        qsim_kernel<true><<<blocks, NTHR>>>((const float4*)inputs, theta,
                                            (float4*)out, n, nthreads);
    }
}